// round 5
// baseline (speedup 1.0000x reference)
#include <cuda_runtime.h>
#include <cstdint>

#define N_NODES 50000
#define N_EDGES 800000
#define D 64
#define N_LAYERS 3

// Scratch (allocation-free rule: __device__ globals). float4 => 16B aligned.
// NOTE: __device__ globals are zero-initialized at module load; g_cnt relies
// on this for the FIRST call, and reorder_kernel re-zeroes it for the next
// call, so every kernel_launch sees cnt == 0 (deterministic).
__device__ float4 g_buf0[N_NODES * D / 4];
__device__ float4 g_buf1[N_NODES * D / 4];
__device__ float4 g_agg [N_NODES * D / 4];
__device__ int    g_cnt   [N_NODES];
__device__ int    g_rowptr[N_NODES + 1];
__device__ int    g_cursor[N_NODES];
__device__ int    g_col   [N_EDGES];

// ---------------------------------------------------------------------------
// CSR build step 1: in-degree histogram (cnt must be 0 on entry; see note)
// ---------------------------------------------------------------------------
__global__ void hist_kernel(const int* __restrict__ dst, int* __restrict__ cnt) {
    int e = blockIdx.x * blockDim.x + threadIdx.x;
    if (e < N_EDGES) atomicAdd(&cnt[dst[e]], 1);
}

// ---------------------------------------------------------------------------
// CSR build step 2: exclusive prefix sum (single block, 1024 threads)
// ---------------------------------------------------------------------------
#define SCAN_THREADS 1024
#define CHUNK ((N_NODES + SCAN_THREADS - 1) / SCAN_THREADS)   // 49

__global__ void __launch_bounds__(SCAN_THREADS) scan_kernel(
        const int* __restrict__ cnt,
        int* __restrict__ rowptr,
        int* __restrict__ cursor) {
    __shared__ int s[SCAN_THREADS];
    const int t = threadIdx.x;
    const int base = t * CHUNK;

    int total = 0;
    #pragma unroll 7
    for (int i = 0; i < CHUNK; i++) {
        int idx = base + i;
        if (idx < N_NODES) total += cnt[idx];
    }
    s[t] = total;
    __syncthreads();

    #pragma unroll
    for (int off = 1; off < SCAN_THREADS; off <<= 1) {
        int v = (t >= off) ? s[t - off] : 0;
        __syncthreads();
        s[t] += v;
        __syncthreads();
    }
    int run = (t == 0) ? 0 : s[t - 1];

    #pragma unroll 7
    for (int i = 0; i < CHUNK; i++) {
        int idx = base + i;
        if (idx < N_NODES) {
            rowptr[idx] = run;
            cursor[idx] = run;
            run += cnt[idx];
        }
    }
    if (t == 0) rowptr[N_NODES] = N_EDGES;
}

// ---------------------------------------------------------------------------
// CSR build step 3: reorder sources into per-destination buckets.
// Also re-zeroes cnt for the NEXT kernel_launch call (cnt is no longer
// needed this call; scan already consumed it).
// ---------------------------------------------------------------------------
__global__ void reorder_kernel(const int* __restrict__ src,
                               const int* __restrict__ dst,
                               int* __restrict__ cursor,
                               int* __restrict__ col,
                               int* __restrict__ cnt) {
    int e = blockIdx.x * blockDim.x + threadIdx.x;
    if (e < N_NODES) cnt[e] = 0;
    if (e >= N_EDGES) return;
    int p = atomicAdd(&cursor[dst[e]], 1);
    col[p] = src[e];
}

// ---------------------------------------------------------------------------
// Aggregation: agg[n] = sum_{e in in(n)} x[col[e]]
// 8 lanes per node, each thread owns 2 float4s (8 floats of the 64-wide row).
// Edge loop unrolled x4 -> 8 independent LDG.128 + 4 col loads in flight.
// No atomics, no zeroing.
// ---------------------------------------------------------------------------
__global__ void __launch_bounds__(256) agg_kernel(
        const float4* __restrict__ x4,
        const int* __restrict__ rowptr,
        const int* __restrict__ col,
        float4* __restrict__ agg4) {
    const int n    = blockIdx.x * 32 + (threadIdx.x >> 3);
    const int lane = threadIdx.x & 7;
    if (n >= N_NODES) return;
    const int beg = rowptr[n];
    const int end = rowptr[n + 1];

    float4 a0 = make_float4(0.f, 0.f, 0.f, 0.f);
    float4 a1 = make_float4(0.f, 0.f, 0.f, 0.f);

    int e = beg;
    for (; e + 4 <= end; e += 4) {
        int s0 = col[e], s1 = col[e + 1], s2 = col[e + 2], s3 = col[e + 3];
        const float4* p0 = x4 + (size_t)s0 * 16 + lane;
        const float4* p1 = x4 + (size_t)s1 * 16 + lane;
        const float4* p2 = x4 + (size_t)s2 * 16 + lane;
        const float4* p3 = x4 + (size_t)s3 * 16 + lane;
        float4 v00 = __ldg(p0),     v01 = __ldg(p0 + 8);
        float4 v10 = __ldg(p1),     v11 = __ldg(p1 + 8);
        float4 v20 = __ldg(p2),     v21 = __ldg(p2 + 8);
        float4 v30 = __ldg(p3),     v31 = __ldg(p3 + 8);
        a0.x += v00.x + v10.x + v20.x + v30.x;
        a0.y += v00.y + v10.y + v20.y + v30.y;
        a0.z += v00.z + v10.z + v20.z + v30.z;
        a0.w += v00.w + v10.w + v20.w + v30.w;
        a1.x += v01.x + v11.x + v21.x + v31.x;
        a1.y += v01.y + v11.y + v21.y + v31.y;
        a1.z += v01.z + v11.z + v21.z + v31.z;
        a1.w += v01.w + v11.w + v21.w + v31.w;
    }
    for (; e < end; e++) {
        const float4* p = x4 + (size_t)col[e] * 16 + lane;
        float4 v0 = __ldg(p), v1 = __ldg(p + 8);
        a0.x += v0.x; a0.y += v0.y; a0.z += v0.z; a0.w += v0.w;
        a1.x += v1.x; a1.y += v1.y; a1.z += v1.z; a1.w += v1.w;
    }
    agg4[(size_t)n * 16 + lane]     = a0;
    agg4[(size_t)n * 16 + 8 + lane] = a1;
}

// ---------------------------------------------------------------------------
// Fused node update: out = relu?( x @ Wself + agg @ Wmsg + b )
// (At the FFMA-pipe floor for fp32; tensor-core rewrite is the next step.)
// ---------------------------------------------------------------------------
#define SMEM_FLOATS (2 * 64 * 64 + 2 * 64 * 65)

__global__ void __launch_bounds__(256) node_gemm_kernel(
        const float* __restrict__ x,
        const float* __restrict__ agg,
        const float* __restrict__ Wself,
        const float* __restrict__ Wmsg,
        const float* __restrict__ bias,
        float* __restrict__ out,
        int apply_relu) {
    extern __shared__ float sm[];
    float* sWs = sm;                    // [64][64]
    float* sWm = sm + 64 * 64;          // [64][64]
    float* sX  = sm + 2 * 64 * 64;      // [64][65] padded
    float* sA  = sX + 64 * 65;          // [64][65] padded

    const int tid     = threadIdx.x;
    const int rowbase = blockIdx.x * 64;

    for (int i = tid; i < 64 * 64 / 4; i += 256) {
        reinterpret_cast<float4*>(sWs)[i] = reinterpret_cast<const float4*>(Wself)[i];
        reinterpret_cast<float4*>(sWm)[i] = reinterpret_cast<const float4*>(Wmsg)[i];
    }
    for (int i = tid; i < 64 * 16; i += 256) {
        int r = i >> 4;
        int c = i & 15;
        int grow = rowbase + r;
        float4 vx = make_float4(0.f, 0.f, 0.f, 0.f);
        float4 va = vx;
        if (grow < N_NODES) {
            vx = reinterpret_cast<const float4*>(x   + (size_t)grow * D)[c];
            va = reinterpret_cast<const float4*>(agg + (size_t)grow * D)[c];
        }
        float* dx = sX + r * 65 + c * 4;
        dx[0] = vx.x; dx[1] = vx.y; dx[2] = vx.z; dx[3] = vx.w;
        float* da = sA + r * 65 + c * 4;
        da[0] = va.x; da[1] = va.y; da[2] = va.z; da[3] = va.w;
    }
    __syncthreads();

    const int r  = tid >> 2;
    const int c0 = (tid & 3) * 16;

    float acc[16];
    #pragma unroll
    for (int j = 0; j < 16; j++) acc[j] = bias[c0 + j];

    #pragma unroll 8
    for (int k = 0; k < 64; k++) {
        float xv = sX[r * 65 + k];
        float av = sA[r * 65 + k];
        #pragma unroll
        for (int j = 0; j < 16; j += 4) {
            float4 ws = *reinterpret_cast<const float4*>(sWs + k * 64 + c0 + j);
            float4 wm = *reinterpret_cast<const float4*>(sWm + k * 64 + c0 + j);
            acc[j + 0] += xv * ws.x + av * wm.x;
            acc[j + 1] += xv * ws.y + av * wm.y;
            acc[j + 2] += xv * ws.z + av * wm.z;
            acc[j + 3] += xv * ws.w + av * wm.w;
        }
    }

    const int grow = rowbase + r;
    if (grow < N_NODES) {
        float* op = out + (size_t)grow * D + c0;
        #pragma unroll
        for (int j = 0; j < 16; j += 4) {
            float4 v;
            v.x = acc[j + 0]; v.y = acc[j + 1]; v.z = acc[j + 2]; v.w = acc[j + 3];
            if (apply_relu) {
                v.x = fmaxf(v.x, 0.f); v.y = fmaxf(v.y, 0.f);
                v.z = fmaxf(v.z, 0.f); v.w = fmaxf(v.w, 0.f);
            }
            *reinterpret_cast<float4*>(op + j) = v;
        }
    }
}

// ---------------------------------------------------------------------------
// Launch. Order puts agg_kernel at our launch index 3 (the one ncu captures).
// ---------------------------------------------------------------------------
extern "C" void kernel_launch(void* const* d_in, const int* in_sizes, int n_in,
                              void* d_out, int out_size) {
    (void)in_sizes; (void)n_in; (void)out_size;

    const float* x0    = (const float*)d_in[0];
    const int*   ei    = (const int*)d_in[1];      // int32 (JAX x64 disabled)
    const float* Wmsg  = (const float*)d_in[2];    // [3][64][64]
    const float* Wself = (const float*)d_in[3];    // [3][64][64]
    const float* bias  = (const float*)d_in[4];    // [3][64]
    float*       out   = (float*)d_out;

    const int* src = ei;
    const int* dst = ei + N_EDGES;

    float4 *buf0, *buf1, *agg;
    int *cnt, *rowptr, *cursor, *col;
    cudaGetSymbolAddress((void**)&buf0,   g_buf0);
    cudaGetSymbolAddress((void**)&buf1,   g_buf1);
    cudaGetSymbolAddress((void**)&agg,    g_agg);
    cudaGetSymbolAddress((void**)&cnt,    g_cnt);
    cudaGetSymbolAddress((void**)&rowptr, g_rowptr);
    cudaGetSymbolAddress((void**)&cursor, g_cursor);
    cudaGetSymbolAddress((void**)&col,    g_col);

    static bool attr_set = false;
    const int smem_bytes = SMEM_FLOATS * (int)sizeof(float);
    if (!attr_set) {
        cudaFuncSetAttribute(node_gemm_kernel,
                             cudaFuncAttributeMaxDynamicSharedMemorySize, smem_bytes);
        attr_set = true;
    }

    // ---- CSR build (cnt == 0 on entry: zero-init at load, re-zeroed by
    //      reorder_kernel each call) ----
    hist_kernel<<<(N_EDGES + 255) / 256, 256>>>(dst, cnt);                 // idx 0
    scan_kernel<<<1, SCAN_THREADS>>>(cnt, rowptr, cursor);                 // idx 1
    reorder_kernel<<<(N_EDGES + 255) / 256, 256>>>(src, dst, cursor, col, cnt); // idx 2

    // ---- Layers ----
    const float* cur[N_LAYERS]  = { x0, (const float*)buf0, (const float*)buf1 };
    float*       next[N_LAYERS] = { (float*)buf0, (float*)buf1, out };

    const int agg_blocks  = (N_NODES + 31) / 32;       // 1563 (32 nodes/block)
    const int gemm_blocks = (N_NODES + 63) / 64;       // 782

    for (int layer = 0; layer < N_LAYERS; layer++) {
        agg_kernel<<<agg_blocks, 256>>>(                                    // idx 3 (layer 0)
            (const float4*)cur[layer], rowptr, col, agg);
        node_gemm_kernel<<<gemm_blocks, 256, smem_bytes>>>(
            cur[layer], (const float*)agg,
            Wself + (size_t)layer * D * D,
            Wmsg  + (size_t)layer * D * D,
            bias  + (size_t)layer * D,
            next[layer],
            layer < N_LAYERS - 1 ? 1 : 0);
    }
}

// round 6
// speedup vs baseline: 1.4570x; 1.4570x over previous
#include <cuda_runtime.h>
#include <cstdint>

#define N_NODES 50000
#define N_EDGES 800000
#define D 64
#define N_LAYERS 3

// Scratch (allocation-free rule: __device__ globals). float4 => 16B aligned.
// g_cnt: zero-initialized at module load; reorder_kernel re-zeroes it each
// call, so every kernel_launch sees cnt == 0 (deterministic).
__device__ float4 g_buf0[N_NODES * D / 4];
__device__ float4 g_buf1[N_NODES * D / 4];
__device__ float4 g_agg [N_NODES * D / 4];
__device__ int    g_cnt   [N_NODES];
__device__ int    g_rowptr[N_NODES + 1];
__device__ int    g_cursor[N_NODES];
__device__ int    g_col   [N_EDGES];

// ---------------------------------------------------------------------------
// f32x2 packed-math helpers (sm_103a; ptxas never auto-fuses these)
// ---------------------------------------------------------------------------
__device__ __forceinline__ unsigned long long fma2(unsigned long long a,
                                                   unsigned long long b,
                                                   unsigned long long c) {
    unsigned long long d;
    asm("fma.rn.f32x2 %0, %1, %2, %3;" : "=l"(d) : "l"(a), "l"(b), "l"(c));
    return d;
}
__device__ __forceinline__ unsigned long long bcast2(float x) {
    unsigned long long d;
    unsigned int xi = __float_as_uint(x);
    asm("mov.b64 %0, {%1, %1};" : "=l"(d) : "r"(xi));
    return d;
}
__device__ __forceinline__ float2 unpack2(unsigned long long v) {
    unsigned int lo, hi;
    asm("mov.b64 {%0, %1}, %2;" : "=r"(lo), "=r"(hi) : "l"(v));
    return make_float2(__uint_as_float(lo), __uint_as_float(hi));
}

// ---------------------------------------------------------------------------
// CSR build step 1: in-degree histogram (cnt must be 0 on entry)
// ---------------------------------------------------------------------------
__global__ void hist_kernel(const int* __restrict__ dst, int* __restrict__ cnt) {
    int e = blockIdx.x * blockDim.x + threadIdx.x;
    if (e < N_EDGES) atomicAdd(&cnt[dst[e]], 1);
}

// ---------------------------------------------------------------------------
// CSR build step 2: exclusive prefix sum (single block, 1024 threads)
// ---------------------------------------------------------------------------
#define SCAN_THREADS 1024
#define CHUNK ((N_NODES + SCAN_THREADS - 1) / SCAN_THREADS)   // 49

__global__ void __launch_bounds__(SCAN_THREADS) scan_kernel(
        const int* __restrict__ cnt,
        int* __restrict__ rowptr,
        int* __restrict__ cursor) {
    __shared__ int s[SCAN_THREADS];
    const int t = threadIdx.x;
    const int base = t * CHUNK;

    int total = 0;
    #pragma unroll 7
    for (int i = 0; i < CHUNK; i++) {
        int idx = base + i;
        if (idx < N_NODES) total += cnt[idx];
    }
    s[t] = total;
    __syncthreads();

    #pragma unroll
    for (int off = 1; off < SCAN_THREADS; off <<= 1) {
        int v = (t >= off) ? s[t - off] : 0;
        __syncthreads();
        s[t] += v;
        __syncthreads();
    }
    int run = (t == 0) ? 0 : s[t - 1];

    #pragma unroll 7
    for (int i = 0; i < CHUNK; i++) {
        int idx = base + i;
        if (idx < N_NODES) {
            rowptr[idx] = run;
            cursor[idx] = run;
            run += cnt[idx];
        }
    }
    if (t == 0) rowptr[N_NODES] = N_EDGES;
}

// ---------------------------------------------------------------------------
// CSR build step 3: reorder; also re-zeroes cnt for the next call
// ---------------------------------------------------------------------------
__global__ void reorder_kernel(const int* __restrict__ src,
                               const int* __restrict__ dst,
                               int* __restrict__ cursor,
                               int* __restrict__ col,
                               int* __restrict__ cnt) {
    int e = blockIdx.x * blockDim.x + threadIdx.x;
    if (e < N_NODES) cnt[e] = 0;
    if (e >= N_EDGES) return;
    int p = atomicAdd(&cursor[dst[e]], 1);
    col[p] = src[e];
}

// ---------------------------------------------------------------------------
// Index-shift dummy: puts node_gemm layer-0 at ncu capture slot (idx 5)
// ---------------------------------------------------------------------------
__global__ void dummy_kernel() {}

// ---------------------------------------------------------------------------
// Aggregation: agg[n] = sum_{e in in(n)} x[col[e]]   (unchanged; 21 us/layer)
// ---------------------------------------------------------------------------
__global__ void __launch_bounds__(256) agg_kernel(
        const float4* __restrict__ x4,
        const int* __restrict__ rowptr,
        const int* __restrict__ col,
        float4* __restrict__ agg4) {
    const int n    = blockIdx.x * 32 + (threadIdx.x >> 3);
    const int lane = threadIdx.x & 7;
    if (n >= N_NODES) return;
    const int beg = rowptr[n];
    const int end = rowptr[n + 1];

    float4 a0 = make_float4(0.f, 0.f, 0.f, 0.f);
    float4 a1 = make_float4(0.f, 0.f, 0.f, 0.f);

    int e = beg;
    for (; e + 4 <= end; e += 4) {
        int s0 = col[e], s1 = col[e + 1], s2 = col[e + 2], s3 = col[e + 3];
        const float4* p0 = x4 + (size_t)s0 * 16 + lane;
        const float4* p1 = x4 + (size_t)s1 * 16 + lane;
        const float4* p2 = x4 + (size_t)s2 * 16 + lane;
        const float4* p3 = x4 + (size_t)s3 * 16 + lane;
        float4 v00 = __ldg(p0),     v01 = __ldg(p0 + 8);
        float4 v10 = __ldg(p1),     v11 = __ldg(p1 + 8);
        float4 v20 = __ldg(p2),     v21 = __ldg(p2 + 8);
        float4 v30 = __ldg(p3),     v31 = __ldg(p3 + 8);
        a0.x += v00.x + v10.x + v20.x + v30.x;
        a0.y += v00.y + v10.y + v20.y + v30.y;
        a0.z += v00.z + v10.z + v20.z + v30.z;
        a0.w += v00.w + v10.w + v20.w + v30.w;
        a1.x += v01.x + v11.x + v21.x + v31.x;
        a1.y += v01.y + v11.y + v21.y + v31.y;
        a1.z += v01.z + v11.z + v21.z + v31.z;
        a1.w += v01.w + v11.w + v21.w + v31.w;
    }
    for (; e < end; e++) {
        const float4* p = x4 + (size_t)col[e] * 16 + lane;
        float4 v0 = __ldg(p), v1 = __ldg(p + 8);
        a0.x += v0.x; a0.y += v0.y; a0.z += v0.z; a0.w += v0.w;
        a1.x += v1.x; a1.y += v1.y; a1.z += v1.z; a1.w += v1.w;
    }
    agg4[(size_t)n * 16 + lane]     = a0;
    agg4[(size_t)n * 16 + 8 + lane] = a1;
}

// ---------------------------------------------------------------------------
// Fused node update v2: out = relu?( x @ Wself + agg @ Wmsg + b )
// 64-row tile, 256 threads. Conflict-free column mapping (q*4 + m*16) and
// packed fma.rn.f32x2 accumulation (2 MACs/instr).
// ---------------------------------------------------------------------------
#define SMEM_FLOATS (2 * 64 * 64 + 2 * 64 * 65)

__global__ void __launch_bounds__(256) node_gemm_kernel(
        const float* __restrict__ x,
        const float* __restrict__ agg,
        const float* __restrict__ Wself,
        const float* __restrict__ Wmsg,
        const float* __restrict__ bias,
        float* __restrict__ out,
        int apply_relu) {
    extern __shared__ float sm[];
    float* sWs = sm;                    // [64][64]
    float* sWm = sm + 64 * 64;          // [64][64]
    float* sX  = sm + 2 * 64 * 64;      // [64][65] padded
    float* sA  = sX + 64 * 65;          // [64][65] padded

    const int tid     = threadIdx.x;
    const int rowbase = blockIdx.x * 64;

    for (int i = tid; i < 64 * 64 / 4; i += 256) {
        reinterpret_cast<float4*>(sWs)[i] = reinterpret_cast<const float4*>(Wself)[i];
        reinterpret_cast<float4*>(sWm)[i] = reinterpret_cast<const float4*>(Wmsg)[i];
    }
    for (int i = tid; i < 64 * 16; i += 256) {
        int r = i >> 4;
        int c = i & 15;
        int grow = rowbase + r;
        float4 vx = make_float4(0.f, 0.f, 0.f, 0.f);
        float4 va = vx;
        if (grow < N_NODES) {
            vx = reinterpret_cast<const float4*>(x   + (size_t)grow * D)[c];
            va = reinterpret_cast<const float4*>(agg + (size_t)grow * D)[c];
        }
        float* dx = sX + r * 65 + c * 4;
        dx[0] = vx.x; dx[1] = vx.y; dx[2] = vx.z; dx[3] = vx.w;
        float* da = sA + r * 65 + c * 4;
        da[0] = va.x; da[1] = va.y; da[2] = va.z; da[3] = va.w;
    }
    __syncthreads();

    const int r = tid >> 2;          // row in tile, 0..63
    const int q = tid & 3;           // column quad base = q*4
    const float* xrow = sX + r * 65;
    const float* arow = sA + r * 65;

    // acc[m*2+p] holds packed output cols (q*4 + m*16 + 2p, +2p+1)
    unsigned long long acc[8];
    #pragma unroll
    for (int m = 0; m < 4; m++) {
        ulonglong2 bv = *reinterpret_cast<const ulonglong2*>(bias + q * 4 + m * 16);
        acc[m * 2 + 0] = bv.x;
        acc[m * 2 + 1] = bv.y;
    }

    #pragma unroll 4
    for (int k = 0; k < 64; k++) {
        unsigned long long xv2 = bcast2(xrow[k]);
        unsigned long long av2 = bcast2(arow[k]);
        const float* wsk = sWs + k * 64 + q * 4;
        const float* wmk = sWm + k * 64 + q * 4;
        #pragma unroll
        for (int m = 0; m < 4; m++) {
            ulonglong2 ws2 = *reinterpret_cast<const ulonglong2*>(wsk + m * 16);
            ulonglong2 wm2 = *reinterpret_cast<const ulonglong2*>(wmk + m * 16);
            acc[m * 2 + 0] = fma2(xv2, ws2.x, acc[m * 2 + 0]);
            acc[m * 2 + 1] = fma2(xv2, ws2.y, acc[m * 2 + 1]);
            acc[m * 2 + 0] = fma2(av2, wm2.x, acc[m * 2 + 0]);
            acc[m * 2 + 1] = fma2(av2, wm2.y, acc[m * 2 + 1]);
        }
    }

    const int grow = rowbase + r;
    if (grow < N_NODES) {
        float* op = out + (size_t)grow * D + q * 4;
        #pragma unroll
        for (int m = 0; m < 4; m++) {
            float2 p0 = unpack2(acc[m * 2 + 0]);
            float2 p1 = unpack2(acc[m * 2 + 1]);
            float4 v = make_float4(p0.x, p0.y, p1.x, p1.y);
            if (apply_relu) {
                v.x = fmaxf(v.x, 0.f); v.y = fmaxf(v.y, 0.f);
                v.z = fmaxf(v.z, 0.f); v.w = fmaxf(v.w, 0.f);
            }
            *reinterpret_cast<float4*>(op + m * 16) = v;
        }
    }
}

// ---------------------------------------------------------------------------
// Launch. dummy at idx 3 puts node_gemm layer-0 at ncu's capture slot (idx 5).
// ---------------------------------------------------------------------------
extern "C" void kernel_launch(void* const* d_in, const int* in_sizes, int n_in,
                              void* d_out, int out_size) {
    (void)in_sizes; (void)n_in; (void)out_size;

    const float* x0    = (const float*)d_in[0];
    const int*   ei    = (const int*)d_in[1];      // int32 (JAX x64 disabled)
    const float* Wmsg  = (const float*)d_in[2];    // [3][64][64]
    const float* Wself = (const float*)d_in[3];    // [3][64][64]
    const float* bias  = (const float*)d_in[4];    // [3][64]
    float*       out   = (float*)d_out;

    const int* src = ei;
    const int* dst = ei + N_EDGES;

    float4 *buf0, *buf1, *agg;
    int *cnt, *rowptr, *cursor, *col;
    cudaGetSymbolAddress((void**)&buf0,   g_buf0);
    cudaGetSymbolAddress((void**)&buf1,   g_buf1);
    cudaGetSymbolAddress((void**)&agg,    g_agg);
    cudaGetSymbolAddress((void**)&cnt,    g_cnt);
    cudaGetSymbolAddress((void**)&rowptr, g_rowptr);
    cudaGetSymbolAddress((void**)&cursor, g_cursor);
    cudaGetSymbolAddress((void**)&col,    g_col);

    static bool attr_set = false;
    const int smem_bytes = SMEM_FLOATS * (int)sizeof(float);
    if (!attr_set) {
        cudaFuncSetAttribute(node_gemm_kernel,
                             cudaFuncAttributeMaxDynamicSharedMemorySize, smem_bytes);
        attr_set = true;
    }

    // ---- CSR build ----
    hist_kernel<<<(N_EDGES + 255) / 256, 256>>>(dst, cnt);                      // 0
    scan_kernel<<<1, SCAN_THREADS>>>(cnt, rowptr, cursor);                      // 1
    reorder_kernel<<<(N_EDGES + 255) / 256, 256>>>(src, dst, cursor, col, cnt); // 2
    dummy_kernel<<<1, 32>>>();                                                  // 3

    // ---- Layers ----
    const float* cur[N_LAYERS]  = { x0, (const float*)buf0, (const float*)buf1 };
    float*       next[N_LAYERS] = { (float*)buf0, (float*)buf1, out };

    const int agg_blocks  = (N_NODES + 31) / 32;       // 1563
    const int gemm_blocks = (N_NODES + 63) / 64;       // 782

    for (int layer = 0; layer < N_LAYERS; layer++) {
        agg_kernel<<<agg_blocks, 256>>>(                       // 4 (layer 0)
            (const float4*)cur[layer], rowptr, col, agg);
        node_gemm_kernel<<<gemm_blocks, 256, smem_bytes>>>(    // 5 (layer 0) <- ncu
            cur[layer], (const float*)agg,
            Wself + (size_t)layer * D * D,
            Wmsg  + (size_t)layer * D * D,
            bias  + (size_t)layer * D,
            next[layer],
            layer < N_LAYERS - 1 ? 1 : 0);
    }
}

// round 7
// speedup vs baseline: 2.0272x; 1.3913x over previous
#include <cuda_runtime.h>
#include <cstdint>

#define N_NODES 50000
#define N_EDGES 800000
#define D 64
#define N_LAYERS 3

// Scratch (allocation-free rule: __device__ globals). float4 => 16B aligned.
// g_cnt: zero-initialized at module load; reorder_kernel re-zeroes it each
// call, so every kernel_launch sees cnt == 0 (deterministic).
__device__ float4 g_buf0[N_NODES * D / 4];
__device__ float4 g_buf1[N_NODES * D / 4];
__device__ float4 g_agg [N_NODES * D / 4];
__device__ int    g_cnt   [N_NODES];
__device__ int    g_rowptr[N_NODES + 1];
__device__ int    g_cursor[N_NODES];
__device__ int    g_col   [N_EDGES];

// ---------------------------------------------------------------------------
// f32x2 packed-math helpers (sm_103a)
// ---------------------------------------------------------------------------
__device__ __forceinline__ unsigned long long fma2(unsigned long long a,
                                                   unsigned long long b,
                                                   unsigned long long c) {
    unsigned long long d;
    asm("fma.rn.f32x2 %0, %1, %2, %3;" : "=l"(d) : "l"(a), "l"(b), "l"(c));
    return d;
}
__device__ __forceinline__ unsigned long long bcast2(float x) {
    unsigned long long d;
    unsigned int xi = __float_as_uint(x);
    asm("mov.b64 %0, {%1, %1};" : "=l"(d) : "r"(xi));
    return d;
}
__device__ __forceinline__ float2 unpack2(unsigned long long v) {
    unsigned int lo, hi;
    asm("mov.b64 {%0, %1}, %2;" : "=r"(lo), "=r"(hi) : "l"(v));
    return make_float2(__uint_as_float(lo), __uint_as_float(hi));
}

// ---------------------------------------------------------------------------
// CSR build step 1: in-degree histogram (cnt must be 0 on entry)
// ---------------------------------------------------------------------------
__global__ void hist_kernel(const int* __restrict__ dst, int* __restrict__ cnt) {
    int e = blockIdx.x * blockDim.x + threadIdx.x;
    if (e < N_EDGES) atomicAdd(&cnt[dst[e]], 1);
}

// ---------------------------------------------------------------------------
// CSR build step 2: exclusive prefix sum (single block, 1024 threads)
// ---------------------------------------------------------------------------
#define SCAN_THREADS 1024
#define CHUNK ((N_NODES + SCAN_THREADS - 1) / SCAN_THREADS)   // 49

__global__ void __launch_bounds__(SCAN_THREADS) scan_kernel(
        const int* __restrict__ cnt,
        int* __restrict__ rowptr,
        int* __restrict__ cursor) {
    __shared__ int s[SCAN_THREADS];
    const int t = threadIdx.x;
    const int base = t * CHUNK;

    int total = 0;
    #pragma unroll 7
    for (int i = 0; i < CHUNK; i++) {
        int idx = base + i;
        if (idx < N_NODES) total += cnt[idx];
    }
    s[t] = total;
    __syncthreads();

    #pragma unroll
    for (int off = 1; off < SCAN_THREADS; off <<= 1) {
        int v = (t >= off) ? s[t - off] : 0;
        __syncthreads();
        s[t] += v;
        __syncthreads();
    }
    int run = (t == 0) ? 0 : s[t - 1];

    #pragma unroll 7
    for (int i = 0; i < CHUNK; i++) {
        int idx = base + i;
        if (idx < N_NODES) {
            rowptr[idx] = run;
            cursor[idx] = run;
            run += cnt[idx];
        }
    }
    if (t == 0) rowptr[N_NODES] = N_EDGES;
}

// ---------------------------------------------------------------------------
// CSR build step 3: reorder; also re-zeroes cnt for the next call
// ---------------------------------------------------------------------------
__global__ void reorder_kernel(const int* __restrict__ src,
                               const int* __restrict__ dst,
                               int* __restrict__ cursor,
                               int* __restrict__ col,
                               int* __restrict__ cnt) {
    int e = blockIdx.x * blockDim.x + threadIdx.x;
    if (e < N_NODES) cnt[e] = 0;
    if (e >= N_EDGES) return;
    int p = atomicAdd(&cursor[dst[e]], 1);
    col[p] = src[e];
}

// ---------------------------------------------------------------------------
// Aggregation: agg[n] = sum_{e in in(n)} x[col[e]]   (21 us/layer measured)
// ---------------------------------------------------------------------------
__global__ void __launch_bounds__(256) agg_kernel(
        const float4* __restrict__ x4,
        const int* __restrict__ rowptr,
        const int* __restrict__ col,
        float4* __restrict__ agg4) {
    const int n    = blockIdx.x * 32 + (threadIdx.x >> 3);
    const int lane = threadIdx.x & 7;
    if (n >= N_NODES) return;
    const int beg = rowptr[n];
    const int end = rowptr[n + 1];

    float4 a0 = make_float4(0.f, 0.f, 0.f, 0.f);
    float4 a1 = make_float4(0.f, 0.f, 0.f, 0.f);

    int e = beg;
    for (; e + 4 <= end; e += 4) {
        int s0 = col[e], s1 = col[e + 1], s2 = col[e + 2], s3 = col[e + 3];
        const float4* p0 = x4 + (size_t)s0 * 16 + lane;
        const float4* p1 = x4 + (size_t)s1 * 16 + lane;
        const float4* p2 = x4 + (size_t)s2 * 16 + lane;
        const float4* p3 = x4 + (size_t)s3 * 16 + lane;
        float4 v00 = __ldg(p0),     v01 = __ldg(p0 + 8);
        float4 v10 = __ldg(p1),     v11 = __ldg(p1 + 8);
        float4 v20 = __ldg(p2),     v21 = __ldg(p2 + 8);
        float4 v30 = __ldg(p3),     v31 = __ldg(p3 + 8);
        a0.x += v00.x + v10.x + v20.x + v30.x;
        a0.y += v00.y + v10.y + v20.y + v30.y;
        a0.z += v00.z + v10.z + v20.z + v30.z;
        a0.w += v00.w + v10.w + v20.w + v30.w;
        a1.x += v01.x + v11.x + v21.x + v31.x;
        a1.y += v01.y + v11.y + v21.y + v31.y;
        a1.z += v01.z + v11.z + v21.z + v31.z;
        a1.w += v01.w + v11.w + v21.w + v31.w;
    }
    for (; e < end; e++) {
        const float4* p = x4 + (size_t)col[e] * 16 + lane;
        float4 v0 = __ldg(p), v1 = __ldg(p + 8);
        a0.x += v0.x; a0.y += v0.y; a0.z += v0.z; a0.w += v0.w;
        a1.x += v1.x; a1.y += v1.y; a1.z += v1.z; a1.w += v1.w;
    }
    agg4[(size_t)n * 16 + lane]     = a0;
    agg4[(size_t)n * 16 + 8 + lane] = a1;
}

// ---------------------------------------------------------------------------
// Fused node update v3: out = relu?( x @ Wself + agg @ Wmsg + b )
// 64-row tile, 256 threads.
//   warp w (0..7)  -> output cols [w*8, w*8+8)   => weight LDS are FULL-warp
//                     broadcast (one address per warp-instr -> 1 wavefront)
//   lane l (0..31) -> rows l and l+32            => weights amortized over 2 rows
// x/agg tiles padded to stride 68 (16B-aligned float4 over k).
// ---------------------------------------------------------------------------
#define XSTRIDE 68
#define SMEM_FLOATS (2 * 64 * 64 + 2 * 64 * XSTRIDE)

__global__ void __launch_bounds__(256) node_gemm_kernel(
        const float* __restrict__ x,
        const float* __restrict__ agg,
        const float* __restrict__ Wself,
        const float* __restrict__ Wmsg,
        const float* __restrict__ bias,
        float* __restrict__ out,
        int apply_relu) {
    extern __shared__ float sm[];
    float* sWs = sm;                    // [64][64]
    float* sWm = sm + 64 * 64;          // [64][64]
    float* sX  = sm + 2 * 64 * 64;      // [64][XSTRIDE]
    float* sA  = sX + 64 * XSTRIDE;     // [64][XSTRIDE]

    const int tid     = threadIdx.x;
    const int rowbase = blockIdx.x * 64;

    for (int i = tid; i < 64 * 64 / 4; i += 256) {
        reinterpret_cast<float4*>(sWs)[i] = reinterpret_cast<const float4*>(Wself)[i];
        reinterpret_cast<float4*>(sWm)[i] = reinterpret_cast<const float4*>(Wmsg)[i];
    }
    for (int i = tid; i < 64 * 16; i += 256) {
        int r = i >> 4;
        int c = i & 15;
        int grow = rowbase + r;
        float4 vx = make_float4(0.f, 0.f, 0.f, 0.f);
        float4 va = vx;
        if (grow < N_NODES) {
            vx = reinterpret_cast<const float4*>(x   + (size_t)grow * D)[c];
            va = reinterpret_cast<const float4*>(agg + (size_t)grow * D)[c];
        }
        *reinterpret_cast<float4*>(sX + r * XSTRIDE + c * 4) = vx;
        *reinterpret_cast<float4*>(sA + r * XSTRIDE + c * 4) = va;
    }
    __syncthreads();

    const int w = tid >> 5;       // warp -> col group base w*8
    const int l = tid & 31;       // lane -> rows l, l+32

    const float* xr0 = sX + l * XSTRIDE;
    const float* xr1 = sX + (l + 32) * XSTRIDE;
    const float* ar0 = sA + l * XSTRIDE;
    const float* ar1 = sA + (l + 32) * XSTRIDE;

    // acc[0..3]: row0 cols w*8..+8 (packed pairs); acc[4..7]: row1
    unsigned long long acc[8];
    {
        ulonglong2 b0 = *reinterpret_cast<const ulonglong2*>(bias + w * 8);
        ulonglong2 b1 = *reinterpret_cast<const ulonglong2*>(bias + w * 8 + 4);
        acc[0] = b0.x; acc[1] = b0.y; acc[2] = b1.x; acc[3] = b1.y;
        acc[4] = b0.x; acc[5] = b0.y; acc[6] = b1.x; acc[7] = b1.y;
    }

    #pragma unroll 4
    for (int k4 = 0; k4 < 64; k4 += 4) {
        float4 xv0 = *reinterpret_cast<const float4*>(xr0 + k4);
        float4 xv1 = *reinterpret_cast<const float4*>(xr1 + k4);
        float4 av0 = *reinterpret_cast<const float4*>(ar0 + k4);
        float4 av1 = *reinterpret_cast<const float4*>(ar1 + k4);
        const float xs0[4] = { xv0.x, xv0.y, xv0.z, xv0.w };
        const float xs1[4] = { xv1.x, xv1.y, xv1.z, xv1.w };
        const float as0[4] = { av0.x, av0.y, av0.z, av0.w };
        const float as1[4] = { av1.x, av1.y, av1.z, av1.w };
        #pragma unroll
        for (int kk = 0; kk < 4; kk++) {
            const int k = k4 + kk;
            const float* wsk = sWs + k * 64 + w * 8;
            const float* wmk = sWm + k * 64 + w * 8;
            // Broadcast loads: same address across all 32 lanes.
            ulonglong2 wsl = *reinterpret_cast<const ulonglong2*>(wsk);
            ulonglong2 wsh = *reinterpret_cast<const ulonglong2*>(wsk + 4);
            ulonglong2 wml = *reinterpret_cast<const ulonglong2*>(wmk);
            ulonglong2 wmh = *reinterpret_cast<const ulonglong2*>(wmk + 4);

            unsigned long long x0b = bcast2(xs0[kk]);
            unsigned long long x1b = bcast2(xs1[kk]);
            unsigned long long a0b = bcast2(as0[kk]);
            unsigned long long a1b = bcast2(as1[kk]);

            acc[0] = fma2(x0b, wsl.x, acc[0]);
            acc[1] = fma2(x0b, wsl.y, acc[1]);
            acc[2] = fma2(x0b, wsh.x, acc[2]);
            acc[3] = fma2(x0b, wsh.y, acc[3]);
            acc[0] = fma2(a0b, wml.x, acc[0]);
            acc[1] = fma2(a0b, wml.y, acc[1]);
            acc[2] = fma2(a0b, wmh.x, acc[2]);
            acc[3] = fma2(a0b, wmh.y, acc[3]);

            acc[4] = fma2(x1b, wsl.x, acc[4]);
            acc[5] = fma2(x1b, wsl.y, acc[5]);
            acc[6] = fma2(x1b, wsh.x, acc[6]);
            acc[7] = fma2(x1b, wsh.y, acc[7]);
            acc[4] = fma2(a1b, wml.x, acc[4]);
            acc[5] = fma2(a1b, wml.y, acc[5]);
            acc[6] = fma2(a1b, wmh.x, acc[6]);
            acc[7] = fma2(a1b, wmh.y, acc[7]);
        }
    }

    #pragma unroll
    for (int rr = 0; rr < 2; rr++) {
        const int grow = rowbase + l + rr * 32;
        if (grow < N_NODES) {
            float* op = out + (size_t)grow * D + w * 8;
            float2 p0 = unpack2(acc[rr * 4 + 0]);
            float2 p1 = unpack2(acc[rr * 4 + 1]);
            float2 p2 = unpack2(acc[rr * 4 + 2]);
            float2 p3 = unpack2(acc[rr * 4 + 3]);
            float4 v0 = make_float4(p0.x, p0.y, p1.x, p1.y);
            float4 v1 = make_float4(p2.x, p2.y, p3.x, p3.y);
            if (apply_relu) {
                v0.x = fmaxf(v0.x, 0.f); v0.y = fmaxf(v0.y, 0.f);
                v0.z = fmaxf(v0.z, 0.f); v0.w = fmaxf(v0.w, 0.f);
                v1.x = fmaxf(v1.x, 0.f); v1.y = fmaxf(v1.y, 0.f);
                v1.z = fmaxf(v1.z, 0.f); v1.w = fmaxf(v1.w, 0.f);
            }
            *reinterpret_cast<float4*>(op)     = v0;
            *reinterpret_cast<float4*>(op + 4) = v1;
        }
    }
}

// ---------------------------------------------------------------------------
// Launch
// ---------------------------------------------------------------------------
extern "C" void kernel_launch(void* const* d_in, const int* in_sizes, int n_in,
                              void* d_out, int out_size) {
    (void)in_sizes; (void)n_in; (void)out_size;

    const float* x0    = (const float*)d_in[0];
    const int*   ei    = (const int*)d_in[1];      // int32 (JAX x64 disabled)
    const float* Wmsg  = (const float*)d_in[2];    // [3][64][64]
    const float* Wself = (const float*)d_in[3];    // [3][64][64]
    const float* bias  = (const float*)d_in[4];    // [3][64]
    float*       out   = (float*)d_out;

    const int* src = ei;
    const int* dst = ei + N_EDGES;

    float4 *buf0, *buf1, *agg;
    int *cnt, *rowptr, *cursor, *col;
    cudaGetSymbolAddress((void**)&buf0,   g_buf0);
    cudaGetSymbolAddress((void**)&buf1,   g_buf1);
    cudaGetSymbolAddress((void**)&agg,    g_agg);
    cudaGetSymbolAddress((void**)&cnt,    g_cnt);
    cudaGetSymbolAddress((void**)&rowptr, g_rowptr);
    cudaGetSymbolAddress((void**)&cursor, g_cursor);
    cudaGetSymbolAddress((void**)&col,    g_col);

    static bool attr_set = false;
    const int smem_bytes = SMEM_FLOATS * (int)sizeof(float);
    if (!attr_set) {
        cudaFuncSetAttribute(node_gemm_kernel,
                             cudaFuncAttributeMaxDynamicSharedMemorySize, smem_bytes);
        attr_set = true;
    }

    // ---- CSR build ----
    hist_kernel<<<(N_EDGES + 255) / 256, 256>>>(dst, cnt);                      // 0
    scan_kernel<<<1, SCAN_THREADS>>>(cnt, rowptr, cursor);                      // 1
    reorder_kernel<<<(N_EDGES + 255) / 256, 256>>>(src, dst, cursor, col, cnt); // 2

    // ---- Layers ----
    const float* cur[N_LAYERS]  = { x0, (const float*)buf0, (const float*)buf1 };
    float*       next[N_LAYERS] = { (float*)buf0, (float*)buf1, out };

    const int agg_blocks  = (N_NODES + 31) / 32;       // 1563
    const int gemm_blocks = (N_NODES + 63) / 64;       // 782

    for (int layer = 0; layer < N_LAYERS; layer++) {
        agg_kernel<<<agg_blocks, 256>>>(                       // 3 (layer 0) <- ncu
            (const float4*)cur[layer], rowptr, col, agg);
        node_gemm_kernel<<<gemm_blocks, 256, smem_bytes>>>(
            cur[layer], (const float*)agg,
            Wself + (size_t)layer * D * D,
            Wmsg  + (size_t)layer * D * D,
            bias  + (size_t)layer * D,
            next[layer],
            layer < N_LAYERS - 1 ? 1 : 0);
    }
}